// round 15
// baseline (speedup 1.0000x reference)
#include <cuda_runtime.h>
#include <cuda_fp16.h>
#include <cstdint>
#include <math.h>

// Problem constants
#define NB    8192
#define TT    48
#define HH    256
#define NENV  10
#define FOURH 1024
#define KPADH 64            // padded feature K (halfs)

// MMA tile config: CTA 128x128, 8 warps (2x4), warp tile 64x32, m16n8k16 fp16
// KT=64 k per stage, swizzled 128B rows, 3 stages, 1 sync/tile, 2 CTAs/SM.
#define BM    128
#define BN    128
#define KT    64
#define ROWB  128           // bytes per A/B smem row (64 halfs)
#define A_BYTES     (BM * ROWB)              // 16384
#define B_BYTES     (BN * ROWB)              // 16384
#define STAGE_BYTES (A_BYTES + B_BYTES)      // 32768
#define LDC   36            // float stride for H/C staging
#define SMEM_DYN (3 * STAGE_BYTES)           // 98304 B

// ---------------------------------------------------------------------------
// Scratch
// ---------------------------------------------------------------------------
__device__ __align__(256) __half g_hH[2][2][NB * HH];   // [layer][pp][n][h]
__device__ __align__(256) float  g_c[2][NB * HH];       // [layer][n][h] fp32
__device__ __align__(256) __half g_featsH[TT * NB * KPADH];
__device__ __align__(256) __half g_WhhH[2][FOURH * HH]; // [r_perm][k]
__device__ __align__(256) __half g_Wih1H[FOURH * HH];
__device__ __align__(256) __half g_WcH[FOURH * KPADH];  // folded W_ih0 @ W_in
__device__ __align__(256) float  g_bias[2][FOURH];      // original layout g*256+h

__device__ __forceinline__ float sigm(float v) {
    return 1.0f / (1.0f + __expf(-v));
}
__device__ __forceinline__ float tanh_fast(float v) {
    return 2.0f / (1.0f + __expf(-2.0f * v)) - 1.0f;
}
__device__ __forceinline__ uint32_t smem_u32(const void* p) {
    return (uint32_t)__cvta_generic_to_shared(p);
}

// Column permutation sigma: permuted gate-row r -> original row (gate*256 + h)
__device__ __forceinline__ int sigma_orig(int r) {
    int blk = r >> 7;
    int c = r & 127;
    int h = blk * 32 + ((c >> 4) << 2) + ((c >> 1) & 3);
    int gate = (((c >> 3) & 1) << 1) | (c & 1);
    return gate * HH + h;
}

// ---------------------------------------------------------------------------
// Prep 1: feats -> half [t][n][64] (pad 0), zero h (slot 0) and c
// ---------------------------------------------------------------------------
__global__ void prep_data(const float* __restrict__ x,
                          const float* __restrict__ coords,
                          const float* __restrict__ env,
                          const float* __restrict__ areas,
                          const float* __restrict__ bird_uv) {
    const int S1 = TT * NB * KPADH;
    const int S2 = 2 * NB * HH;
    const int tot = S1 + S2 + S2;
    for (int idx = blockIdx.x * blockDim.x + threadIdx.x; idx < tot;
         idx += gridDim.x * blockDim.x) {
        if (idx < S1) {
            int f = idx & 63;
            int n = (idx >> 6) & (NB - 1);
            int t = idx >> 19;
            float v = 0.0f;
            if (f == 0)       v = x[(size_t)n * TT + t];
            else if (f <= 2)  v = coords[n * 2 + (f - 1)];
            else if (f <= 12) v = env[((size_t)n * NENV + (f - 3)) * TT + t];
            else if (f == 13) v = areas[n];
            else if (f <= 15) v = bird_uv[((size_t)n * 2 + (f - 14)) * TT + t];
            g_featsH[idx] = __float2half_rn(v);
        } else if (idx < S1 + S2) {
            int j = idx - S1;
            int l = j / (NB * HH);
            g_hH[l][0][j - l * NB * HH] = __float2half_rn(0.0f);
        } else {
            int j = idx - S1 - S2;
            int l = j / (NB * HH);
            g_c[l][j - l * NB * HH] = 0.0f;
        }
    }
}

// ---------------------------------------------------------------------------
// Prep 2: weights (sigma-permuted rows, half), biases, folded Wc (k pad 64)
// ---------------------------------------------------------------------------
__global__ void prep_wts(const float* __restrict__ W_in,
                         const float* __restrict__ W_ih,
                         const float* __restrict__ W_hh,
                         const float* __restrict__ b_ih,
                         const float* __restrict__ b_hh) {
    const int T1 = 524288;
    const int T2 = T1 + 262144;
    const int T3 = T2 + 2048;
    const int tot = T3 + FOURH * KPADH;
    for (int i = blockIdx.x * blockDim.x + threadIdx.x; i < tot;
         i += gridDim.x * blockDim.x) {
        if (i < T1) {
            int l = i >> 18;
            int rem = i & 262143;
            int r = rem >> 8;
            int k = rem & 255;
            g_WhhH[l][rem] =
                __float2half_rn(W_hh[l * 262144 + sigma_orig(r) * HH + k]);
        } else if (i < T2) {
            int rem = i - T1;
            int r = rem >> 8;
            int k = rem & 255;
            g_Wih1H[rem] =
                __float2half_rn(W_ih[262144 + sigma_orig(r) * HH + k]);
        } else if (i < T3) {
            int j = i - T2;
            int l = j >> 10;
            int s = j & 1023;
            g_bias[l][s] = b_ih[l * FOURH + s] + b_hh[l * FOURH + s];
        } else {
            int j = i - T3;
            int k = j & 63;
            int r = j >> 6;
            float out = 0.0f;
            if (k < 16) {
                const float* wr = W_ih + sigma_orig(r) * HH;   // layer 0
                float acc = 0.0f;
                #pragma unroll 8
                for (int m = 0; m < HH; m++)
                    acc = fmaf(wr[m], W_in[m * 16 + k], acc);
                out = acc;
            }
            g_WcH[j] = __float2half_rn(out);
        }
    }
}

// ---------------------------------------------------------------------------
// Fused mma.sync fp16 LSTM wavefront step — BM=128, templated, unrolled
// ---------------------------------------------------------------------------
__device__ __forceinline__ void issue_tile(const __half* __restrict__ Ab, int as,
                                           const __half* __restrict__ Bb, int bs,
                                           int k0, uint32_t smb, int st,
                                           int rowbase, int gbase, int tid) {
    uint32_t stA = smb + st * STAGE_BYTES;
    uint32_t stB = stA + A_BYTES;
    // A: 128 rows x 8 chunks = 1024 cp.async (4 per thread)
    #pragma unroll
    for (int jj = 0; jj < 4; jj++) {
        int idx = tid + jj * 256;
        int row = idx >> 3, ch = idx & 7;
        int chs = ch ^ (row & 7);
        const __half* src = Ab + (size_t)(rowbase + row) * as + k0 + ch * 8;
        uint32_t d = stA + row * ROWB + chs * 16;
        asm volatile("cp.async.cg.shared.global [%0], [%1], 16;"
                     :: "r"(d), "l"(src));
    }
    // B: 128 rows x 8 chunks = 1024 cp.async (4 per thread)
    #pragma unroll
    for (int jj = 0; jj < 4; jj++) {
        int idx = tid + jj * 256;
        int row = idx >> 3, ch = idx & 7;
        int chs = ch ^ (row & 7);
        const __half* src = Bb + (size_t)(gbase + row) * bs + k0 + ch * 8;
        uint32_t d = stB + row * ROWB + chs * 16;
        asm volatile("cp.async.cg.shared.global [%0], [%1], 16;"
                     :: "r"(d), "l"(src));
    }
    asm volatile("cp.async.commit_group;");
}

__device__ __forceinline__ void mma_f16(float* d, const uint32_t* a,
                                        const uint32_t* b) {
    asm volatile(
        "mma.sync.aligned.m16n8k16.row.col.f32.f16.f16.f32 "
        "{%0,%1,%2,%3}, {%4,%5,%6,%7}, {%8,%9}, {%0,%1,%2,%3};"
        : "+f"(d[0]), "+f"(d[1]), "+f"(d[2]), "+f"(d[3])
        : "r"(a[0]), "r"(a[1]), "r"(a[2]), "r"(a[3]), "r"(b[0]), "r"(b[1]));
}

__device__ __forceinline__ void ldm_x4(uint32_t* r, uint32_t addr) {
    asm volatile(
        "ldmatrix.sync.aligned.m8n8.x4.shared.b16 {%0,%1,%2,%3}, [%4];"
        : "=r"(r[0]), "=r"(r[1]), "=r"(r[2]), "=r"(r[3]) : "r"(addr));
}

template <int LAYER>
__device__ __forceinline__ void lstm_body(int t, char* dynC,
                                          float* __restrict__ out) {
    const uint32_t smb = smem_u32(dynC);
    const int tid = threadIdx.x;
    const int wid = tid >> 5;
    const int lane = tid & 31;
    const int gid = lane >> 2;
    const int tig = lane & 3;
    const int wm = (wid & 1) * 64;        // warp row base (4 m-tiles)
    const int wn = (wid >> 1) * 32;       // warp col base (4 n-tiles)
    const int rowbase = blockIdx.x * BM;
    const int gbase = blockIdx.y * BN;
    const int hb = blockIdx.y * 32;

    const int l7 = lane & 7;
    const uint32_t aRow = (uint32_t)(wm + ((lane >> 3) & 1) * 8 + l7) * ROWB;
    const uint32_t bRow = (uint32_t)(wn + ((lane >> 4) & 1) * 8 + l7) * ROWB +
                          A_BYTES;
    const int c0a = (lane >> 4) & 1;
    const int c0b = (lane >> 3) & 1;

    // --- compile-time operand config ---
    constexpr int K0T = (LAYER == 0) ? 1 : 4;
    constexpr int TK = K0T + HH / KT;             // 5 or 8
    constexpr int A0S = (LAYER == 0) ? KPADH : HH;
    constexpr int B0S = (LAYER == 0) ? KPADH : HH;

    const __half* A0 = (LAYER == 0)
        ? g_featsH + (size_t)t * NB * KPADH
        : g_hH[0][(t + 1) & 1];
    const __half* B0 = (LAYER == 0) ? g_WcH : g_Wih1H;
    const __half* A1 = g_hH[LAYER][t & 1];
    const __half* B1 = g_WhhH[LAYER];

    float acc[4][4][4];
    #pragma unroll
    for (int i = 0; i < 4; i++)
        #pragma unroll
        for (int j = 0; j < 4; j++)
            #pragma unroll
            for (int k = 0; k < 4; k++) acc[i][j][k] = 0.0f;

    // prologue: stages 0 and 1
    issue_tile(A0, A0S, B0, B0S, 0, smb, 0, rowbase, gbase, tid);
    if (1 < K0T)
        issue_tile(A0, A0S, B0, B0S, KT, smb, 1, rowbase, gbase, tid);
    else
        issue_tile(A1, HH, B1, HH, 0, smb, 1, rowbase, gbase, tid);

    #pragma unroll
    for (int kt = 0; kt < TK; kt++) {
        if (kt == TK - 1) asm volatile("cp.async.wait_group 0;");
        else              asm volatile("cp.async.wait_group 1;");
        __syncthreads();

        if (kt + 2 < TK) {
            const int j = kt + 2;
            if (j < K0T)
                issue_tile(A0, A0S, B0, B0S, j * KT, smb, (kt + 2) % 3,
                           rowbase, gbase, tid);
            else
                issue_tile(A1, HH, B1, HH, (j - K0T) * KT, smb,
                           (kt + 2) % 3, rowbase, gbase, tid);
        }

        const uint32_t stage = smb + (kt % 3) * STAGE_BYTES;
        const uint32_t aB = stage + aRow;
        const uint32_t bB = stage + bRow;

        #pragma unroll
        for (int kk = 0; kk < 4; kk++) {
            const uint32_t chA = (uint32_t)(((kk * 2 + c0a) ^ l7) << 4);
            const uint32_t chB = (uint32_t)(((kk * 2 + c0b) ^ l7) << 4);
            uint32_t a[4][4];
            #pragma unroll
            for (int mt = 0; mt < 4; mt++)
                ldm_x4(a[mt], aB + (uint32_t)(mt * 16 * ROWB) + chA);
            uint32_t b[2][4];
            #pragma unroll
            for (int p = 0; p < 2; p++)
                ldm_x4(b[p], bB + (uint32_t)(p * 16 * ROWB) + chB);
            #pragma unroll
            for (int mt = 0; mt < 4; mt++)
                #pragma unroll
                for (int nt = 0; nt < 4; nt++)
                    mma_f16(acc[mt][nt], a[mt], &b[nt >> 1][(nt & 1) * 2]);
        }
    }
    __syncthreads();   // all stages free -> reuse stages 0/1 for H/C staging

    // --- LSTM cell epilogue (fp32); old c loaded directly from gmem ---
    float* Hs = (float*)dynC;                       // 128*36*4 = 18432 B
    float* Cw = (float*)(dynC + 18432);             // 18432 B
    int hq[2];
    float bb[2][4];
    #pragma unroll
    for (int q = 0; q < 2; q++) {
        int hl = ((wid >> 1) * 2 + q) * 4 + tig;
        hq[q] = hl;
        #pragma unroll
        for (int g = 0; g < 4; g++)
            bb[q][g] = g_bias[LAYER][g * HH + hb + hl];
    }

    const float* cgl = g_c[LAYER];
    #pragma unroll
    for (int mt = 0; mt < 4; mt++)
        #pragma unroll
        for (int q = 0; q < 2; q++)
            #pragma unroll
            for (int rr = 0; rr < 2; rr++) {
                int row = wm + mt * 16 + gid + rr * 8;
                float co = cgl[(size_t)(rowbase + row) * HH + hb + hq[q]];
                float iv = sigm(acc[mt][2 * q][rr * 2 + 0] + bb[q][0]);
                float fv = sigm(acc[mt][2 * q][rr * 2 + 1] + bb[q][1]);
                float gv = tanh_fast(acc[mt][2 * q + 1][rr * 2 + 0] + bb[q][2]);
                float ov = sigm(acc[mt][2 * q + 1][rr * 2 + 1] + bb[q][3]);
                float cn = fv * co + iv * gv;
                float hn = ov * tanh_fast(cn);
                Cw[row * LDC + hq[q]] = cn;
                Hs[row * LDC + hq[q]] = hn;
            }
    __syncthreads();

    // --- coalesced write-out: half state, fp32 c, fp32 final output ---
    __half* hgH = g_hH[LAYER][(t + 1) & 1] + (size_t)rowbase * HH + hb;
    float* cg = g_c[LAYER] + (size_t)rowbase * HH + hb;
    const size_t NH = (size_t)NB * HH;
    float* oh = out + (size_t)LAYER * NH + (size_t)rowbase * HH + hb;
    float* oc = out + (size_t)(2 + LAYER) * NH + (size_t)rowbase * HH + hb;
    const bool last = (t == TT - 1);

    #pragma unroll
    for (int j = 0; j < 4; j++) {
        int idx = tid + j * 256;
        int row = idx >> 3, ch = idx & 7;
        float4 hv = *(const float4*)&Hs[row * LDC + ch * 4];
        float4 cv = *(const float4*)&Cw[row * LDC + ch * 4];
        *(float4*)(cg + (size_t)row * HH + ch * 4) = cv;
        __half2 p0 = __floats2half2_rn(hv.x, hv.y);
        __half2 p1 = __floats2half2_rn(hv.z, hv.w);
        __half2* hd = (__half2*)(hgH + (size_t)row * HH + ch * 4);
        hd[0] = p0;
        hd[1] = p1;
        if (last) {
            *(float4*)(oh + (size_t)row * HH + ch * 4) = hv;
            *(float4*)(oc + (size_t)row * HH + ch * 4) = cv;
        }
    }
}

__global__ __launch_bounds__(256, 2) void lstm_step_mma(int kstep,
                                                        float* __restrict__ out) {
    const int layer = blockIdx.z;
    const int t = (layer == 0) ? kstep : kstep - 1;
    if (t < 0 || t >= TT) return;

    extern __shared__ __align__(16) char dynC[];
    if (layer == 0) lstm_body<0>(t, dynC, out);
    else            lstm_body<1>(t, dynC, out);
}

// ---------------------------------------------------------------------------
extern "C" void kernel_launch(void* const* d_in, const int* in_sizes, int n_in,
                              void* d_out, int out_size) {
    const float* x       = (const float*)d_in[0];
    const float* coords  = (const float*)d_in[1];
    const float* env     = (const float*)d_in[2];
    const float* areas   = (const float*)d_in[3];
    const float* bird_uv = (const float*)d_in[4];
    const float* W_in    = (const float*)d_in[5];
    const float* W_ih    = (const float*)d_in[6];
    const float* W_hh    = (const float*)d_in[7];
    const float* b_ih    = (const float*)d_in[8];
    const float* b_hh    = (const float*)d_in[9];
    (void)in_sizes; (void)n_in; (void)out_size;

    cudaFuncSetAttribute(lstm_step_mma,
                         cudaFuncAttributeMaxDynamicSharedMemorySize, SMEM_DYN);

    prep_data<<<8192, 256>>>(x, coords, env, areas, bird_uv);
    prep_wts<<<832, 256>>>(W_in, W_ih, W_hh, b_ih, b_hh);

    dim3 grid(NB / BM, FOURH / BN, 2);   // (64, 8, 2) wavefront over layers
    for (int k = 0; k <= TT; k++)
        lstm_step_mma<<<grid, 256, SMEM_DYN>>>(k, (float*)d_out);
}

// round 16
// speedup vs baseline: 1.1133x; 1.1133x over previous
#include <cuda_runtime.h>
#include <cuda_fp16.h>
#include <cstdint>
#include <math.h>

// Problem constants
#define NB    8192
#define TT    48
#define HH    256
#define NENV  10
#define FOURH 1024
#define KF    16            // true feature K (halfs), no padding

// MMA tile config: CTA 64x128, 8 warps (2x4), warp tile 32x32, m16n8k16 fp16
// KT=64 k per stage, swizzled 128B rows, 3 stages, 1 sync/tile, 3 CTAs/SM.
#define BM    64
#define BN    128
#define KT    64
#define ROWB  128           // bytes per A/B smem row (64 halfs)
#define A_BYTES     (BM * ROWB)              // 8192
#define B_BYTES     (BN * ROWB)              // 16384
#define STAGE_BYTES (A_BYTES + B_BYTES)      // 24576
#define LDC   36            // float stride for H/C staging
#define SMEM_DYN (3 * STAGE_BYTES)           // 73728 B

// ---------------------------------------------------------------------------
// Scratch
// ---------------------------------------------------------------------------
__device__ __align__(256) __half g_hH[2][2][NB * HH];   // [layer][pp][n][h]
__device__ __align__(256) float  g_c[2][NB * HH];       // [layer][n][h] fp32
__device__ __align__(256) __half g_featsH[TT * NB * KF]; // [t][n][16]
__device__ __align__(256) __half g_WhhH[2][FOURH * HH]; // [r_perm][k]
__device__ __align__(256) __half g_Wih1H[FOURH * HH];
__device__ __align__(256) __half g_WcH[FOURH * KF];     // folded W_ih0 @ W_in
__device__ __align__(256) float  g_bias[2][FOURH];      // original layout g*256+h

__device__ __forceinline__ float sigm(float v) {
    return 1.0f / (1.0f + __expf(-v));
}
__device__ __forceinline__ float tanh_fast(float v) {
    return 2.0f / (1.0f + __expf(-2.0f * v)) - 1.0f;
}
__device__ __forceinline__ uint32_t smem_u32(const void* p) {
    return (uint32_t)__cvta_generic_to_shared(p);
}

// Column permutation sigma: permuted gate-row r -> original row (gate*256 + h)
__device__ __forceinline__ int sigma_orig(int r) {
    int blk = r >> 7;
    int c = r & 127;
    int h = blk * 32 + ((c >> 4) << 2) + ((c >> 1) & 3);
    int gate = (((c >> 3) & 1) << 1) | (c & 1);
    return gate * HH + h;
}

// ---------------------------------------------------------------------------
// Prep 1: feats -> half [t][n][16], zero h (slot 0) and c
// ---------------------------------------------------------------------------
__global__ void prep_data(const float* __restrict__ x,
                          const float* __restrict__ coords,
                          const float* __restrict__ env,
                          const float* __restrict__ areas,
                          const float* __restrict__ bird_uv) {
    const int S1 = TT * NB * KF;
    const int S2 = 2 * NB * HH;
    const int tot = S1 + S2 + S2;
    for (int idx = blockIdx.x * blockDim.x + threadIdx.x; idx < tot;
         idx += gridDim.x * blockDim.x) {
        if (idx < S1) {
            int f = idx & 15;
            int n = (idx >> 4) & (NB - 1);
            int t = idx >> 17;
            float v;
            if (f == 0)       v = x[(size_t)n * TT + t];
            else if (f <= 2)  v = coords[n * 2 + (f - 1)];
            else if (f <= 12) v = env[((size_t)n * NENV + (f - 3)) * TT + t];
            else if (f == 13) v = areas[n];
            else              v = bird_uv[((size_t)n * 2 + (f - 14)) * TT + t];
            g_featsH[idx] = __float2half_rn(v);
        } else if (idx < S1 + S2) {
            int j = idx - S1;
            int l = j / (NB * HH);
            g_hH[l][0][j - l * NB * HH] = __float2half_rn(0.0f);
        } else {
            int j = idx - S1 - S2;
            int l = j / (NB * HH);
            g_c[l][j - l * NB * HH] = 0.0f;
        }
    }
}

// ---------------------------------------------------------------------------
// Prep 2: weights (sigma-permuted rows, half), biases, folded Wc (K=16)
// ---------------------------------------------------------------------------
__global__ void prep_wts(const float* __restrict__ W_in,
                         const float* __restrict__ W_ih,
                         const float* __restrict__ W_hh,
                         const float* __restrict__ b_ih,
                         const float* __restrict__ b_hh) {
    const int T1 = 524288;
    const int T2 = T1 + 262144;
    const int T3 = T2 + 2048;
    const int tot = T3 + FOURH * KF;
    for (int i = blockIdx.x * blockDim.x + threadIdx.x; i < tot;
         i += gridDim.x * blockDim.x) {
        if (i < T1) {
            int l = i >> 18;
            int rem = i & 262143;
            int r = rem >> 8;
            int k = rem & 255;
            g_WhhH[l][rem] =
                __float2half_rn(W_hh[l * 262144 + sigma_orig(r) * HH + k]);
        } else if (i < T2) {
            int rem = i - T1;
            int r = rem >> 8;
            int k = rem & 255;
            g_Wih1H[rem] =
                __float2half_rn(W_ih[262144 + sigma_orig(r) * HH + k]);
        } else if (i < T3) {
            int j = i - T2;
            int l = j >> 10;
            int s = j & 1023;
            g_bias[l][s] = b_ih[l * FOURH + s] + b_hh[l * FOURH + s];
        } else {
            int j = i - T3;
            int k = j & 15;
            int r = j >> 4;
            const float* wr = W_ih + sigma_orig(r) * HH;   // layer 0
            float acc = 0.0f;
            #pragma unroll 8
            for (int m = 0; m < HH; m++)
                acc = fmaf(wr[m], W_in[m * 16 + k], acc);
            g_WcH[j] = __float2half_rn(acc);
        }
    }
}

// ---------------------------------------------------------------------------
// Fused mma.sync fp16 LSTM wavefront step (BM=64, 3 CTAs/SM, templated)
// ---------------------------------------------------------------------------
__device__ __forceinline__ void issue_tile(const __half* __restrict__ Ab, int as,
                                           const __half* __restrict__ Bb, int bs,
                                           int k0, uint32_t smb, int st,
                                           int rowbase, int gbase, int tid) {
    uint32_t stA = smb + st * STAGE_BYTES;
    uint32_t stB = stA + A_BYTES;
    #pragma unroll
    for (int jj = 0; jj < 2; jj++) {
        int idx = tid + jj * 256;
        int row = idx >> 3, ch = idx & 7;
        int chs = ch ^ (row & 7);
        const __half* src = Ab + (size_t)(rowbase + row) * as + k0 + ch * 8;
        uint32_t d = stA + row * ROWB + chs * 16;
        asm volatile("cp.async.cg.shared.global [%0], [%1], 16;"
                     :: "r"(d), "l"(src));
    }
    #pragma unroll
    for (int jj = 0; jj < 4; jj++) {
        int idx = tid + jj * 256;
        int row = idx >> 3, ch = idx & 7;
        int chs = ch ^ (row & 7);
        const __half* src = Bb + (size_t)(gbase + row) * bs + k0 + ch * 8;
        uint32_t d = stB + row * ROWB + chs * 16;
        asm volatile("cp.async.cg.shared.global [%0], [%1], 16;"
                     :: "r"(d), "l"(src));
    }
    asm volatile("cp.async.commit_group;");
}

// Feats tile: A 64x16, B 128x16 (logical chunks 0..1 only, swizzled placement)
__device__ __forceinline__ void issue_feats(const __half* __restrict__ Ab,
                                            const __half* __restrict__ Bb,
                                            uint32_t smb, int st,
                                            int rowbase, int gbase, int tid) {
    uint32_t stA = smb + st * STAGE_BYTES;
    uint32_t stB = stA + A_BYTES;
    int row = tid >> 1;
    int ch = tid & 1;
    if (tid < 128) {                          // A: 64 rows x 2 chunks
        int chs = ch ^ (row & 7);
        const __half* src = Ab + (size_t)(rowbase + row) * KF + ch * 8;
        uint32_t d = stA + row * ROWB + chs * 16;
        asm volatile("cp.async.cg.shared.global [%0], [%1], 16;"
                     :: "r"(d), "l"(src));
    }
    {                                          // B: 128 rows x 2 chunks
        int chs = ch ^ (row & 7);
        const __half* src = Bb + (size_t)(gbase + row) * KF + ch * 8;
        uint32_t d = stB + row * ROWB + chs * 16;
        asm volatile("cp.async.cg.shared.global [%0], [%1], 16;"
                     :: "r"(d), "l"(src));
    }
    asm volatile("cp.async.commit_group;");
}

__device__ __forceinline__ void mma_f16(float* d, const uint32_t* a,
                                        const uint32_t* b) {
    asm volatile(
        "mma.sync.aligned.m16n8k16.row.col.f32.f16.f16.f32 "
        "{%0,%1,%2,%3}, {%4,%5,%6,%7}, {%8,%9}, {%0,%1,%2,%3};"
        : "+f"(d[0]), "+f"(d[1]), "+f"(d[2]), "+f"(d[3])
        : "r"(a[0]), "r"(a[1]), "r"(a[2]), "r"(a[3]), "r"(b[0]), "r"(b[1]));
}

__device__ __forceinline__ void ldm_x4(uint32_t* r, uint32_t addr) {
    asm volatile(
        "ldmatrix.sync.aligned.m8n8.x4.shared.b16 {%0,%1,%2,%3}, [%4];"
        : "=r"(r[0]), "=r"(r[1]), "=r"(r[2]), "=r"(r[3]) : "r"(addr));
}

// One stage of MMA work: KKN kk-steps (4 = full 64-wide tile, 1 = feats tile)
template <int KKN>
__device__ __forceinline__ void mma_block(uint32_t aB, uint32_t bB,
                                          int c0a, int c0b, int l7,
                                          float acc[2][4][4]) {
    #pragma unroll
    for (int kk = 0; kk < KKN; kk++) {
        const uint32_t chA = (uint32_t)(((kk * 2 + c0a) ^ l7) << 4);
        const uint32_t chB = (uint32_t)(((kk * 2 + c0b) ^ l7) << 4);
        uint32_t a[2][4];
        #pragma unroll
        for (int mt = 0; mt < 2; mt++)
            ldm_x4(a[mt], aB + (uint32_t)(mt * 16 * ROWB) + chA);
        uint32_t b[2][4];
        #pragma unroll
        for (int p = 0; p < 2; p++)
            ldm_x4(b[p], bB + (uint32_t)(p * 16 * ROWB) + chB);
        #pragma unroll
        for (int mt = 0; mt < 2; mt++)
            #pragma unroll
            for (int nt = 0; nt < 4; nt++)
                mma_f16(acc[mt][nt], a[mt], &b[nt >> 1][(nt & 1) * 2]);
    }
}

template <int LAYER>
__device__ __forceinline__ void lstm_body(int t, char* dynC,
                                          float* __restrict__ out) {
    const uint32_t smb = smem_u32(dynC);
    const int tid = threadIdx.x;
    const int wid = tid >> 5;
    const int lane = tid & 31;
    const int gid = lane >> 2;
    const int tig = lane & 3;
    const int wm = (wid & 1) * 32;
    const int wn = (wid >> 1) * 32;
    const int rowbase = blockIdx.x * BM;
    const int gbase = blockIdx.y * BN;
    const int hb = blockIdx.y * 32;

    const int l7 = lane & 7;
    const uint32_t aRow = (uint32_t)(wm + ((lane >> 3) & 1) * 8 + l7) * ROWB;
    const uint32_t bRow = (uint32_t)(wn + ((lane >> 4) & 1) * 8 + l7) * ROWB +
                          A_BYTES;
    const int c0a = (lane >> 4) & 1;
    const int c0b = (lane >> 3) & 1;

    // --- compile-time tile schedule ---
    // LAYER 0: kt=0 feats (1 kk), kt=1..4 Whh0     (TK=5)
    // LAYER 1: kt=0..3 Wih1,      kt=4..7 Whh1     (TK=8)
    constexpr int K0T = (LAYER == 0) ? 1 : 4;
    constexpr int TK = K0T + HH / KT;

    const __half* A0 = (LAYER == 0)
        ? g_featsH + (size_t)t * NB * KF
        : g_hH[0][(t + 1) & 1];
    const __half* B0 = (LAYER == 0) ? g_WcH : g_Wih1H;
    const __half* A1 = g_hH[LAYER][t & 1];
    const __half* B1 = g_WhhH[LAYER];

    float acc[2][4][4];
    #pragma unroll
    for (int i = 0; i < 2; i++)
        #pragma unroll
        for (int j = 0; j < 4; j++)
            #pragma unroll
            for (int k = 0; k < 4; k++) acc[i][j][k] = 0.0f;

    // prologue: stages 0 and 1
    if (LAYER == 0) {
        issue_feats(A0, B0, smb, 0, rowbase, gbase, tid);
        issue_tile(A1, HH, B1, HH, 0, smb, 1, rowbase, gbase, tid);
    } else {
        issue_tile(A0, HH, B0, HH, 0, smb, 0, rowbase, gbase, tid);
        issue_tile(A0, HH, B0, HH, KT, smb, 1, rowbase, gbase, tid);
    }

    #pragma unroll
    for (int kt = 0; kt < TK; kt++) {
        if (kt == TK - 1) asm volatile("cp.async.wait_group 0;");
        else              asm volatile("cp.async.wait_group 1;");
        __syncthreads();

        if (kt + 2 < TK) {
            const int j = kt + 2;
            if (j < K0T)
                issue_tile(A0, HH, B0, HH, j * KT, smb, (kt + 2) % 3,
                           rowbase, gbase, tid);
            else
                issue_tile(A1, HH, B1, HH, (j - K0T) * KT, smb,
                           (kt + 2) % 3, rowbase, gbase, tid);
        }

        const uint32_t stage = smb + (kt % 3) * STAGE_BYTES;
        const uint32_t aB = stage + aRow;
        const uint32_t bB = stage + bRow;

        if (LAYER == 0 && kt == 0)
            mma_block<1>(aB, bB, c0a, c0b, l7, acc);   // feats: K=16 only
        else
            mma_block<4>(aB, bB, c0a, c0b, l7, acc);
    }
    __syncthreads();   // all stages free -> reuse stage 0 for H/C staging

    // --- LSTM cell epilogue (fp32); old c loaded directly from gmem ---
    float* Hs = (float*)dynC;                       // 64*36*4 = 9216 B
    float* Cw = (float*)(dynC + 9216);              // 9216 B (fits stage0)
    int hq[2];
    float bb[2][4];
    #pragma unroll
    for (int q = 0; q < 2; q++) {
        int hl = ((wid >> 1) * 2 + q) * 4 + tig;
        hq[q] = hl;
        #pragma unroll
        for (int g = 0; g < 4; g++)
            bb[q][g] = g_bias[LAYER][g * HH + hb + hl];
    }

    const float* cgl = g_c[LAYER];
    #pragma unroll
    for (int mt = 0; mt < 2; mt++)
        #pragma unroll
        for (int q = 0; q < 2; q++)
            #pragma unroll
            for (int rr = 0; rr < 2; rr++) {
                int row = wm + mt * 16 + gid + rr * 8;
                float co = cgl[(size_t)(rowbase + row) * HH + hb + hq[q]];
                float iv = sigm(acc[mt][2 * q][rr * 2 + 0] + bb[q][0]);
                float fv = sigm(acc[mt][2 * q][rr * 2 + 1] + bb[q][1]);
                float gv = tanh_fast(acc[mt][2 * q + 1][rr * 2 + 0] + bb[q][2]);
                float ov = sigm(acc[mt][2 * q + 1][rr * 2 + 1] + bb[q][3]);
                float cn = fv * co + iv * gv;
                float hn = ov * tanh_fast(cn);
                Cw[row * LDC + hq[q]] = cn;
                Hs[row * LDC + hq[q]] = hn;
            }
    __syncthreads();

    // --- coalesced write-out: half state, fp32 c, fp32 final output ---
    __half* hgH = g_hH[LAYER][(t + 1) & 1] + (size_t)rowbase * HH + hb;
    float* cg = g_c[LAYER] + (size_t)rowbase * HH + hb;
    const size_t NH = (size_t)NB * HH;
    float* oh = out + (size_t)LAYER * NH + (size_t)rowbase * HH + hb;
    float* oc = out + (size_t)(2 + LAYER) * NH + (size_t)rowbase * HH + hb;
    const bool last = (t == TT - 1);

    #pragma unroll
    for (int j = 0; j < 2; j++) {
        int idx = tid + j * 256;
        int row = idx >> 3, ch = idx & 7;
        float4 hv = *(const float4*)&Hs[row * LDC + ch * 4];
        float4 cv = *(const float4*)&Cw[row * LDC + ch * 4];
        *(float4*)(cg + (size_t)row * HH + ch * 4) = cv;
        __half2 p0 = __floats2half2_rn(hv.x, hv.y);
        __half2 p1 = __floats2half2_rn(hv.z, hv.w);
        __half2* hd = (__half2*)(hgH + (size_t)row * HH + ch * 4);
        hd[0] = p0;
        hd[1] = p1;
        if (last) {
            *(float4*)(oh + (size_t)row * HH + ch * 4) = hv;
            *(float4*)(oc + (size_t)row * HH + ch * 4) = cv;
        }
    }
}

__global__ __launch_bounds__(256, 3) void lstm_step_mma(int kstep,
                                                        float* __restrict__ out) {
    const int layer = blockIdx.z;
    const int t = (layer == 0) ? kstep : kstep - 1;
    if (t < 0 || t >= TT) return;

    extern __shared__ __align__(16) char dynC[];
    if (layer == 0) lstm_body<0>(t, dynC, out);
    else            lstm_body<1>(t, dynC, out);
}

// ---------------------------------------------------------------------------
extern "C" void kernel_launch(void* const* d_in, const int* in_sizes, int n_in,
                              void* d_out, int out_size) {
    const float* x       = (const float*)d_in[0];
    const float* coords  = (const float*)d_in[1];
    const float* env     = (const float*)d_in[2];
    const float* areas   = (const float*)d_in[3];
    const float* bird_uv = (const float*)d_in[4];
    const float* W_in    = (const float*)d_in[5];
    const float* W_ih    = (const float*)d_in[6];
    const float* W_hh    = (const float*)d_in[7];
    const float* b_ih    = (const float*)d_in[8];
    const float* b_hh    = (const float*)d_in[9];
    (void)in_sizes; (void)n_in; (void)out_size;

    cudaFuncSetAttribute(lstm_step_mma,
                         cudaFuncAttributeMaxDynamicSharedMemorySize, SMEM_DYN);

    prep_data<<<4096, 256>>>(x, coords, env, areas, bird_uv);
    prep_wts<<<832, 256>>>(W_in, W_ih, W_hh, b_ih, b_hh);

    dim3 grid(NB / BM, FOURH / BN, 2);   // (128, 8, 2) wavefront over layers
    for (int k = 0; k <= TT; k++)
        lstm_step_mma<<<grid, 256, SMEM_DYN>>>(k, (float*)d_out);
}